// round 16
// baseline (speedup 1.0000x reference)
#include <cuda_runtime.h>
#include <cuda_bf16.h>
#include <cstdint>
#include <math.h>

// ---------------- problem constants ----------------
#define U_N   10000
#define G_N   3000
#define I_N   8000
#define B_N   4096
#define LM    20

// ---------------- scratch layout (floats) ----------------
constexpr int OFF_UI_A = 0;        // 576000  UI l2
constexpr int OFF_UI_B = 576000;   // 576000  UI l1
constexpr int OFF_UI_C = 1152000;  // 576000  UI l3
constexpr int OFF_GI_A = 1728000;  // 352000  GI l2
constexpr int OFF_GI_B = 2080000;  // 352000  GI l1
constexpr int OFF_GI_C = 2432000;  // 352000  GI l3
constexpr int OFF_YS   = 2784000;  // 320000  user social term 1
constexpr int OFF_UM   = 3104000;  // 320000  user social term 2
constexpr int OFF_YI   = 3424000;  // 256000  item social term 1
constexpr int OFF_IM   = 3680000;  // 256000  item social term 2
// end of zeroed region (3936000)
constexpr int OFF_USUM = 3936000;  // 320000
constexpr int OFF_IEU  = 4256000;  // 256000
constexpr int OFF_GIIS = 4512000;  // 256000
constexpr int OFF_GSUM = 4768000;  // 96000
constexpr int OFF_GUL  = 4864000;  // 96000
constexpr int OFF_W    = 4960000;  // 6400
constexpr int OFF_GF   = 4966400;  // 96000
constexpr int SCRATCH_TOTAL = 5062400;

__device__ float d_scratch[SCRATCH_TOTAL];

// bf16 copies of the overlap matrices (converted once per launch)
constexpr size_t ABF_U = (size_t)U_N * U_N;           // 100,000,000
constexpr size_t ABF_I = (size_t)I_N * I_N;           //  64,000,000
__device__ __nv_bfloat16 d_Abf[ABF_U + ABF_I + 4096];

// ---------------- elementwise helpers ----------------
__global__ void k_zero4(float4* p, int n4) {
    int i = blockIdx.x * blockDim.x + threadIdx.x;
    if (i < n4) p[i] = make_float4(0.f, 0.f, 0.f, 0.f);
}

// fp32 -> bf16 (rn) matrix convert, 4 elems/thread
__global__ void k_cvt(const float4* __restrict__ src, uint2* __restrict__ dst, int n4) {
    int i = blockIdx.x * blockDim.x + threadIdx.x;
    if (i >= n4) return;
    float4 v = src[i];
    __nv_bfloat162 lo = __floats2bfloat162_rn(v.x, v.y);
    __nv_bfloat162 hi = __floats2bfloat162_rn(v.z, v.w);
    uint2 o;
    o.x = *(uint32_t*)&lo;
    o.y = *(uint32_t*)&hi;
    dst[i] = o;
}

__device__ __forceinline__ float4 add4(float4 a, float4 b) {
    return make_float4(a.x+b.x, a.y+b.y, a.z+b.z, a.w+b.w);
}
__device__ __forceinline__ float4 mul4(float4 a, float s) {
    return make_float4(a.x*s, a.y*s, a.z*s, a.w*s);
}

__global__ void k_comb_ui(float* __restrict__ S, const float4* __restrict__ uemb,
                          const float4* __restrict__ iemb, const float4* __restrict__ gemb) {
    int i = blockIdx.x * blockDim.x + threadIdx.x;
    const float4* A = (const float4*)(S + OFF_UI_A);
    const float4* B = (const float4*)(S + OFF_UI_B);
    const float4* C = (const float4*)(S + OFF_UI_C);
    if (i < 80000) {
        float4 s = add4(add4(uemb[i], B[i]), add4(A[i], C[i]));
        ((float4*)(S + OFF_USUM))[i] = s;
    } else if (i < 144000) {
        int j = i - 80000;
        float4 s = add4(add4(iemb[j], B[i]), add4(A[i], C[i]));
        ((float4*)(S + OFF_IEU))[j] = mul4(s, 0.25f);
    } else if (i < 168000) {
        int j = i - 144000;
        ((float4*)(S + OFF_GSUM))[j] = gemb[j];
    }
}

__global__ void k_comb_gi(float* __restrict__ S) {
    int i = blockIdx.x * blockDim.x + threadIdx.x;
    if (i >= 64000) return;
    int j = G_N * 8 + i;
    const float4* A = (const float4*)(S + OFF_GI_A);
    const float4* B = (const float4*)(S + OFF_GI_B);
    const float4* C = (const float4*)(S + OFF_GI_C);
    const float4* E = (const float4*)(S + OFF_IEU);
    ((float4*)(S + OFF_GIIS))[i] = add4(add4(E[i], B[j]), add4(A[j], C[j]));
}

// ---------------- COO SpMM: 8 edges/warp, 2-way ILP per lane ----------------
__device__ __forceinline__ void red4(float* p, float a, float b, float c, float d) {
    asm volatile("red.global.add.v4.f32 [%0], {%1, %2, %3, %4};"
                 :: "l"(p), "f"(a), "f"(b), "f"(c), "f"(d) : "memory");
}
__global__ void k_spmm(const int* __restrict__ rows, const int* __restrict__ cols,
                       const float* __restrict__ vals, int nnz,
                       const float* __restrict__ x0, const float* __restrict__ x1,
                       int split, float* __restrict__ out, int row_limit) {
    int gw = (blockIdx.x * blockDim.x + threadIdx.x) >> 5;
    int lane = threadIdx.x & 31;
    int e0 = gw << 3;
    if (e0 >= nnz) return;
    int ld = 0;
    int half = lane >> 4;
    int hl = lane & 15;
    int which = hl >> 2;
    int j4 = e0 + half * 4 + (hl & 3);
    if (which < 3 && j4 < nnz) {
        if (which == 0)      ld = __ldg(rows + j4);
        else if (which == 1) ld = __ldg(cols + j4);
        else                 ld = __float_as_int(__ldg(vals + j4));
    }
    int subw = lane >> 3;
    int l4   = (lane & 7) << 2;
    int rA =                 __shfl_sync(0xffffffffu, ld, subw);
    int cA =                 __shfl_sync(0xffffffffu, ld, 4 + subw);
    float vA = __int_as_float(__shfl_sync(0xffffffffu, ld, 8 + subw));
    int rB =                 __shfl_sync(0xffffffffu, ld, 16 + subw);
    int cB =                 __shfl_sync(0xffffffffu, ld, 20 + subw);
    float vB = __int_as_float(__shfl_sync(0xffffffffu, ld, 24 + subw));
    int eA = e0 + subw, eB = e0 + 4 + subw;
    bool doA = (eA < nnz) && (rA < row_limit);
    bool doB = (eB < nnz) && (rB < row_limit);
    float4 xa, xb;
    if (doA) {
        const float* s = (cA < split) ? x0 + ((size_t)cA << 5)
                                      : x1 + ((size_t)(cA - split) << 5);
        xa = *(const float4*)(s + l4);
    }
    if (doB) {
        const float* s = (cB < split) ? x0 + ((size_t)cB << 5)
                                      : x1 + ((size_t)(cB - split) << 5);
        xb = *(const float4*)(s + l4);
    }
    if (doA) red4(out + ((size_t)rA << 5) + l4, vA*xa.x, vA*xa.y, vA*xa.z, vA*xa.w);
    if (doB) red4(out + ((size_t)rB << 5) + l4, vB*xb.x, vB*xb.y, vB*xb.z, vB*xb.w);
}

// ---------------- tensor-core dense MM: y += Abf16 @ x ----------------
// A pre-converted bf16 in DRAM, streamed via cp.async into a 4-stage smem ring
// (80 B padded rows, conflict-free ldmatrix). x fp32 -> bf16 hi+lo in-kernel
// (2-stage, convert-after-mma). acc = A*(x_hi + x_lo).
#define MMKC 32
#define MALD 40
#define NSTAGE 4
#define A_ST (128 * MALD)
#define X_ST (MMKC * MALD)

__device__ __forceinline__ uint32_t cvta_s(const void* p) {
    return (uint32_t)__cvta_generic_to_shared(p);
}
__device__ __forceinline__ void ldm_x4(uint32_t* r, uint32_t addr) {
    asm volatile("ldmatrix.sync.aligned.m8n8.x4.shared.b16 {%0,%1,%2,%3}, [%4];"
                 : "=r"(r[0]), "=r"(r[1]), "=r"(r[2]), "=r"(r[3]) : "r"(addr));
}
__device__ __forceinline__ void ldm_x4_t(uint32_t* r, uint32_t addr) {
    asm volatile("ldmatrix.sync.aligned.m8n8.x4.trans.shared.b16 {%0,%1,%2,%3}, [%4];"
                 : "=r"(r[0]), "=r"(r[1]), "=r"(r[2]), "=r"(r[3]) : "r"(addr));
}
__device__ __forceinline__ void mma_bf16(float* d, const uint32_t* a,
                                         uint32_t b0, uint32_t b1) {
    asm volatile("mma.sync.aligned.m16n8k16.row.col.f32.bf16.bf16.f32 "
                 "{%0,%1,%2,%3}, {%4,%5,%6,%7}, {%8,%9}, {%0,%1,%2,%3};"
                 : "+f"(d[0]), "+f"(d[1]), "+f"(d[2]), "+f"(d[3])
                 : "r"(a[0]), "r"(a[1]), "r"(a[2]), "r"(a[3]), "r"(b0), "r"(b1));
}
__device__ __forceinline__ void red2(float* p, float a, float b) {
    asm volatile("red.global.add.v2.f32 [%0], {%1, %2};"
                 :: "l"(p), "f"(a), "f"(b) : "memory");
}
__device__ __forceinline__ void st_split4(float4 v, __nv_bfloat16* hd, __nv_bfloat16* ldst) {
    uint32_t x0 = __float_as_uint(v.x), x1 = __float_as_uint(v.y);
    uint32_t x2 = __float_as_uint(v.z), x3 = __float_as_uint(v.w);
    uint32_t h01, h23;
    asm("prmt.b32 %0, %1, %2, 0x7632;" : "=r"(h01) : "r"(x0), "r"(x1));
    asm("prmt.b32 %0, %1, %2, 0x7632;" : "=r"(h23) : "r"(x2), "r"(x3));
    float l0 = v.x - __uint_as_float(x0 & 0xFFFF0000u);
    float l1 = v.y - __uint_as_float(x1 & 0xFFFF0000u);
    float l2 = v.z - __uint_as_float(x2 & 0xFFFF0000u);
    float l3 = v.w - __uint_as_float(x3 & 0xFFFF0000u);
    uint32_t lo01, lo23;
    asm("prmt.b32 %0, %1, %2, 0x7632;" : "=r"(lo01)
        : "r"(__float_as_uint(l0)), "r"(__float_as_uint(l1)));
    asm("prmt.b32 %0, %1, %2, 0x7632;" : "=r"(lo23)
        : "r"(__float_as_uint(l2)), "r"(__float_as_uint(l3)));
    *(uint2*)hd   = make_uint2(h01, h23);
    *(uint2*)ldst = make_uint2(lo01, lo23);
}

__global__ void __launch_bounds__(256, 3)
k_mm_tc(const __nv_bfloat16* __restrict__ Abf, const float* __restrict__ x,
        float* __restrict__ y, int n) {
    __shared__ __nv_bfloat16 Asm[NSTAGE][A_ST];
    __shared__ __nv_bfloat16 Xh[2][X_ST], Xl[2][X_ST];
    int tid = threadIdx.x;
    int warp = tid >> 5, lane = tid & 31;
    int m0 = blockIdx.x * 128;

    int nchunks = (n + MMKC - 1) / MMKC;
    int per = (nchunks + gridDim.y - 1) / gridDim.y;
    int ci0 = blockIdx.y * per;
    int ci1 = min(nchunks, ci0 + per);

    float acc[4][4];
    #pragma unroll
    for (int f = 0; f < 4; f++)
        #pragma unroll
        for (int j = 0; j < 4; j++) acc[f][j] = 0.f;

    uint32_t smemA0 = cvta_s(&Asm[0][0]);
    uint32_t aAddr0 = cvta_s(&Asm[0][(warp * 16 + (lane & 15)) * MALD + ((lane >> 4) << 3)]);
    uint32_t xBaseH0 = cvta_s(&Xh[0][(lane & 15) * MALD + ((lane >> 4) << 3)]);
    uint32_t xBaseL0 = cvta_s(&Xl[0][(lane & 15) * MALD + ((lane >> 4) << 3)]);

    // cp.async staging indices: 512 (row,seg) units, 2 per thread
    int r0i = tid >> 2, s0i = tid & 3;           // pass 0: rows 0..63
    int r1i = (tid + 256) >> 2, s1i = tid & 3;   // pass 1: rows 64..127
    int g0 = m0 + r0i; if (g0 > n - 1) g0 = n - 1;
    int g1 = m0 + r1i; if (g1 > n - 1) g1 = n - 1;
    const __nv_bfloat16* src0 = Abf + (size_t)g0 * n + s0i * 8;
    const __nv_bfloat16* src1 = Abf + (size_t)g1 * n + s1i * 8;
    uint32_t dst0 = smemA0 + r0i * (MALD * 2) + s0i * 16;
    uint32_t dst1 = smemA0 + r1i * (MALD * 2) + s1i * 16;

    int xr = tid >> 3, xc = (tid & 7) << 2;
    float4 xR;
    const float4 Z4 = make_float4(0.f, 0.f, 0.f, 0.f);

    #define ISSUE_A(ci) do {                                                    \
        int _k0 = (ci) * MMKC;                                                  \
        uint32_t _so = (uint32_t)((ci) % NSTAGE) * (A_ST * 2);                  \
        asm volatile("cp.async.cg.shared.global [%0], [%1], 16;"                \
                     :: "r"(dst0 + _so), "l"(src0 + _k0) : "memory");           \
        asm volatile("cp.async.cg.shared.global [%0], [%1], 16;"                \
                     :: "r"(dst1 + _so), "l"(src1 + _k0) : "memory");           \
    } while (0)

    // ---- prologue: issue A chunks ci0..ci0+NSTAGE-2; load+convert x(ci0) ----
    #pragma unroll
    for (int pc = 0; pc < NSTAGE - 1; pc++) {
        int ci = ci0 + pc;
        if (ci < ci1) ISSUE_A(ci);
        asm volatile("cp.async.commit_group;" ::: "memory");
    }
    if (ci0 < ci1) {
        int k0 = ci0 * MMKC;
        xR = Z4;
        if (k0 + xr < n) xR = *(const float4*)(x + (size_t)(k0 + xr) * 32 + xc);
        int s = ci0 & 1;
        st_split4(xR, &Xh[s][xr * MALD + xc], &Xl[s][xr * MALD + xc]);
    }

    for (int ci = ci0; ci < ci1; ci++) {
        asm volatile("cp.async.wait_group %0;" :: "n"(NSTAGE - 2) : "memory");
        __syncthreads();
        // issue chunk ci+NSTAGE-1 into stage (ci-1)%NSTAGE (safe: mma(ci-1) done)
        if (ci + NSTAGE - 1 < ci1) ISSUE_A(ci + NSTAGE - 1);
        asm volatile("cp.async.commit_group;" ::: "memory");
        bool more = (ci + 1 < ci1);
        if (more) {
            int k0 = (ci + 1) * MMKC;
            xR = Z4;
            if (k0 + xr < n) xR = *(const float4*)(x + (size_t)(k0 + xr) * 32 + xc);
        }
        // MMA on stage ci
        uint32_t aOff = (uint32_t)(ci % NSTAGE) * (A_ST * 2);
        uint32_t xOff = (uint32_t)(ci & 1) * (X_ST * 2);
        #pragma unroll
        for (int ks = 0; ks < MMKC; ks += 16) {
            uint32_t afh[4];
            ldm_x4(afh, aAddr0 + aOff + ks * 2);
            #pragma unroll
            for (int np = 0; np < 2; np++) {
                uint32_t bh[4], bl[4];
                uint32_t off = (uint32_t)(ks * MALD + np * 16) * 2;
                ldm_x4_t(bh, xBaseH0 + xOff + off);
                ldm_x4_t(bl, xBaseL0 + xOff + off);
                mma_bf16(acc[np * 2 + 0], afh, bh[0], bh[1]);
                mma_bf16(acc[np * 2 + 1], afh, bh[2], bh[3]);
                mma_bf16(acc[np * 2 + 0], afh, bl[0], bl[1]);
                mma_bf16(acc[np * 2 + 1], afh, bl[2], bl[3]);
            }
        }
        // convert x(ci+1) into the other X stage (after mma; barrier-protected)
        if (more) {
            int s = (ci + 1) & 1;
            st_split4(xR, &Xh[s][xr * MALD + xc], &Xl[s][xr * MALD + xc]);
        }
    }
    #undef ISSUE_A

    int gr8 = lane >> 2, cc = (lane & 3) * 2;
    #pragma unroll
    for (int f = 0; f < 4; f++) {
        int nc = f * 8 + cc;
        int r0 = m0 + warp * 16 + gr8;
        int r1 = r0 + 8;
        if (r0 < n) red2(y + (size_t)r0 * 32 + nc, acc[f][0], acc[f][1]);
        if (r1 < n) red2(y + (size_t)r1 * 32 + nc, acc[f][2], acc[f][3]);
    }
}

// ---------------- group_userlayer ----------------
__global__ void k_gul(float* __restrict__ gul, const int* __restrict__ users,
                      const float* __restrict__ mask, const float* __restrict__ t0,
                      const float* __restrict__ t1, const float* __restrict__ t2) {
    int i = blockIdx.x * blockDim.x + threadIdx.x;
    if (i >= G_N * 32) return;
    int g = i >> 5, d = i & 31;
    float s = 0.f;
    #pragma unroll
    for (int l = 0; l < LM; l++) {
        int u = __ldg(users + g * LM + l);
        size_t o = ((size_t)u << 5) + d;
        float acc = __ldg(t0 + o) + __ldg(t1 + o) + __ldg(t2 + o);
        s = fmaf(__ldg(mask + g * LM + l), acc, s);
    }
    gul[i] = 0.25f * s;
}

// ---------------- gate MLP ----------------
__global__ void k_gate(float* __restrict__ w, const float* __restrict__ gsum,
                       const float* __restrict__ gl2, const float* __restrict__ gul,
                       const float* __restrict__ w1, const float* __restrict__ b1,
                       const float* __restrict__ w2, const float* __restrict__ b2) {
    int wid = (blockIdx.x * blockDim.x + threadIdx.x) >> 5;
    int lane = threadIdx.x & 31;
    if (wid >= 2 * G_N) return;
    float xd;
    if (wid < G_N) {
        size_t o = (size_t)wid * 32 + lane;
        xd = 0.25f * (__ldg(gsum + o) + __ldg(gl2 + o));
    } else {
        xd = __ldg(gul + (size_t)(wid - G_N) * 32 + lane);
    }
    float h = b1[lane];
    #pragma unroll
    for (int d = 0; d < 32; d++) {
        float a = __shfl_sync(0xffffffffu, xd, d);
        h = fmaf(a, __ldg(w1 + d * 32 + lane), h);
    }
    h = fmaxf(h, 0.f);
    float t = h * __ldg(w2 + lane);
    #pragma unroll
    for (int o = 16; o > 0; o >>= 1) t += __shfl_xor_sync(0xffffffffu, t, o);
    if (lane == 0) w[wid] = 1.f / (1.f + expf(-(t + b2[0])));
}

__global__ void k_combine(float* __restrict__ gf, const float* __restrict__ w,
                          const float* __restrict__ gsum, const float* __restrict__ gl2,
                          const float* __restrict__ gul) {
    int i = blockIdx.x * blockDim.x + threadIdx.x;
    if (i >= G_N * 32) return;
    int g = i >> 5;
    gf[i] = w[g] * 0.25f * (gsum[i] + gl2[i]) + w[G_N + g] * gul[i];
}

// ---------------- predict MLP ----------------
__global__ void k_pred(float* __restrict__ out, const int* __restrict__ gin,
                       const int* __restrict__ iin, const float* __restrict__ gf,
                       const float* __restrict__ t0, const float* __restrict__ t1,
                       const float* __restrict__ t2,
                       const float* __restrict__ pw1, const float* __restrict__ pb1,
                       const float* __restrict__ pw2, const float* __restrict__ pb2) {
    int wid = (blockIdx.x * blockDim.x + threadIdx.x) >> 5;
    int lane = threadIdx.x & 31;
    if (wid >= B_N) return;
    int g = __ldg(gin + wid), it = __ldg(iin + wid);
    size_t o = ((size_t)it << 5) + lane;
    float ia = 0.25f * (__ldg(t0 + o) + __ldg(t1 + o) + __ldg(t2 + o));
    float e = __ldg(gf + (size_t)g * 32 + lane) * ia;
    float s = 0.f;
    #pragma unroll
    for (int j = 0; j < 8; j++) {
        float p = e * __ldg(pw1 + lane * 8 + j);
        #pragma unroll
        for (int o2 = 16; o2 > 0; o2 >>= 1) p += __shfl_xor_sync(0xffffffffu, p, o2);
        s += fmaxf(p + pb1[j], 0.f) * pw2[j];
    }
    if (lane == 0) out[wid] = 1.f / (1.f + expf(-(s + pb2[0])));
}

// ---------------- host driver ----------------
static inline int cdiv(int a, int b) { return (a + b - 1) / b; }

extern "C" void kernel_launch(void* const* d_in, const int* in_sizes, int n_in,
                              void* d_out, int out_size) {
    const int*   gin  = (const int*)  d_in[0];
    const int*   iin  = (const int*)  d_in[1];
    const float* uemb = (const float*)d_in[2];
    const float* gemb = (const float*)d_in[3];
    const float* iemb = (const float*)d_in[4];
    const int*   ui_r = (const int*)  d_in[5];
    const int*   ui_c = (const int*)  d_in[6];
    const float* ui_v = (const float*)d_in[7];
    const int*   gi_r = (const int*)  d_in[8];
    const int*   gi_c = (const int*)  d_in[9];
    const float* gi_v = (const float*)d_in[10];
    const float* ovu  = (const float*)d_in[11];
    const float* ovi  = (const float*)d_in[12];
    const int*   agu  = (const int*)  d_in[13];
    const float* agm  = (const float*)d_in[14];
    const float* gw1  = (const float*)d_in[15];
    const float* gb1  = (const float*)d_in[16];
    const float* gw2  = (const float*)d_in[17];
    const float* gb2  = (const float*)d_in[18];
    const float* pw1  = (const float*)d_in[19];
    const float* pb1  = (const float*)d_in[20];
    const float* pw2  = (const float*)d_in[21];
    const float* pb2  = (const float*)d_in[22];
    float* out = (float*)d_out;
    const int nnz_ui = in_sizes[5];
    const int nnz_gi = in_sizes[8];

    float* S = nullptr;
    cudaGetSymbolAddress((void**)&S, d_scratch);
    __nv_bfloat16* Abf = nullptr;
    cudaGetSymbolAddress((void**)&Abf, d_Abf);

    const int TPB = 256;
    int spmm_ui_grid = cdiv(nnz_ui * 4, TPB);
    int spmm_gi_grid = cdiv(nnz_gi * 4, TPB);

    cudaStream_t s2, s3;
    cudaStreamCreateWithFlags(&s2, cudaStreamNonBlocking);
    cudaStreamCreateWithFlags(&s3, cudaStreamNonBlocking);
    cudaEvent_t evRoot, evCvtU, evUsum, evCvtI, evJoinU;
    cudaEventCreateWithFlags(&evRoot, cudaEventDisableTiming);
    cudaEventCreateWithFlags(&evCvtU, cudaEventDisableTiming);
    cudaEventCreateWithFlags(&evUsum, cudaEventDisableTiming);
    cudaEventCreateWithFlags(&evCvtI, cudaEventDisableTiming);
    cudaEventCreateWithFlags(&evJoinU, cudaEventDisableTiming);

    // ---- fork root ----
    cudaEventRecord(evRoot, 0);
    cudaStreamWaitEvent(s2, evRoot, 0);

    // s2: convert ovu -> bf16 (prioritized), later runs the user MM chain
    k_cvt<<<cdiv((int)(ABF_U / 4), TPB), TPB, 0, s2>>>((const float4*)ovu,
                                                       (uint2*)Abf, (int)(ABF_U / 4));
    cudaEventRecord(evCvtU, s2);
    // s3: convert ovi -> bf16 after ovu finishes
    cudaStreamWaitEvent(s3, evCvtU, 0);
    k_cvt<<<cdiv((int)(ABF_I / 4), TPB), TPB, 0, s3>>>((const float4*)ovi,
                                                       (uint2*)(Abf + ABF_U),
                                                       (int)(ABF_I / 4));
    cudaEventRecord(evCvtI, s3);

    // main: zero accumulation buffers, UI chain
    k_zero4<<<cdiv(984000,TPB),TPB>>>((float4*)S, 984000);
    k_spmm<<<spmm_ui_grid,TPB>>>(ui_r, ui_c, ui_v, nnz_ui, uemb, iemb, U_N,
                                 S + OFF_UI_B, U_N + I_N);
    k_spmm<<<spmm_ui_grid,TPB>>>(ui_r, ui_c, ui_v, nnz_ui,
                                 S + OFF_UI_B, S + OFF_UI_B + U_N*32, U_N,
                                 S + OFF_UI_A, U_N + I_N);
    k_spmm<<<spmm_ui_grid,TPB>>>(ui_r, ui_c, ui_v, nnz_ui,
                                 S + OFF_UI_A, S + OFF_UI_A + U_N*32, U_N,
                                 S + OFF_UI_C, U_N + I_N);
    k_comb_ui<<<cdiv(168000,TPB),TPB>>>(S, (const float4*)uemb,
                                        (const float4*)iemb, (const float4*)gemb);
    cudaEventRecord(evUsum, 0);

    // s2: user social MM chain (after ovu convert [program order] + USUM)
    cudaStreamWaitEvent(s2, evUsum, 0);
    {
        dim3 g(cdiv(U_N, 128), 11);
        k_mm_tc<<<g, 256, 0, s2>>>(Abf, S + OFF_USUM, S + OFF_YS, U_N);
        k_mm_tc<<<g, 256, 0, s2>>>(Abf, S + OFF_YS,   S + OFF_UM, U_N);
    }
    cudaEventRecord(evJoinU, s2);

    // main: GI chain
    k_spmm<<<spmm_gi_grid,TPB>>>(gi_r, gi_c, gi_v, nnz_gi, gemb, S + OFF_IEU, G_N,
                                 S + OFF_GI_B, G_N + I_N);
    k_spmm<<<spmm_gi_grid,TPB>>>(gi_r, gi_c, gi_v, nnz_gi,
                                 S + OFF_GI_B, S + OFF_GI_B + G_N*32, G_N,
                                 S + OFF_GI_A, G_N + I_N);
    k_spmm<<<spmm_gi_grid,TPB>>>(gi_r, gi_c, gi_v, nnz_gi,
                                 S + OFF_GI_A, S + OFF_GI_A + G_N*32, G_N,
                                 S + OFF_GI_C, G_N + I_N);
    k_spmm<<<spmm_gi_grid,TPB>>>(gi_r, gi_c, gi_v, nnz_gi, gemb, iemb, G_N,
                                 S + OFF_GSUM, G_N);
    k_spmm<<<spmm_gi_grid,TPB>>>(gi_r, gi_c, gi_v, nnz_gi, gemb, S + OFF_UI_A + U_N*32,
                                 G_N, S + OFF_GSUM, G_N);
    k_comb_gi<<<cdiv(64000,TPB),TPB>>>(S);

    // main: item social MM chain (needs ovi bf16)
    cudaStreamWaitEvent(0, evCvtI, 0);
    {
        dim3 g(cdiv(I_N, 128), 14);
        k_mm_tc<<<g, 256>>>(Abf + ABF_U, S + OFF_GIIS, S + OFF_YI, I_N);
        k_mm_tc<<<g, 256>>>(Abf + ABF_U, S + OFF_YI,   S + OFF_IM, I_N);
    }

    // join user branch
    cudaStreamWaitEvent(0, evJoinU, 0);

    // ======== pooling, gate, predict ========
    k_gul<<<cdiv(G_N*32, TPB), TPB>>>(S + OFF_GUL, agu, agm,
                                      S + OFF_USUM, S + OFF_YS, S + OFF_UM);
    k_gate<<<cdiv(2*G_N*32, TPB), TPB>>>(S + OFF_W, S + OFF_GSUM, S + OFF_GI_A,
                                         S + OFF_GUL, gw1, gb1, gw2, gb2);
    k_combine<<<cdiv(G_N*32, TPB), TPB>>>(S + OFF_GF, S + OFF_W, S + OFF_GSUM,
                                          S + OFF_GI_A, S + OFF_GUL);
    k_pred<<<cdiv(B_N*32, TPB), TPB>>>(out, gin, iin, S + OFF_GF,
                                       S + OFF_GIIS, S + OFF_YI, S + OFF_IM,
                                       pw1, pb1, pw2, pb2);

    cudaEventDestroy(evRoot);
    cudaEventDestroy(evCvtU);
    cudaEventDestroy(evUsum);
    cudaEventDestroy(evCvtI);
    cudaEventDestroy(evJoinU);
    cudaStreamDestroy(s2);
    cudaStreamDestroy(s3);
}